// round 9
// baseline (speedup 1.0000x reference)
#include <cuda_runtime.h>

// SIREN fused inference, GB300 sm_103a — R9.
// R8 profile: fma 68%, L1 50%, occ 12.4%, issue 46% — staging copies + 9
// syncs/layer serialize against the fma pipe. R9: weights read directly from
// pre-transposed g_WT via __ldg float4 (L1/L2-resident, 8x intra-CTA reuse);
// WS buffer and all k-loop syncs removed (2 syncs/layer). Smem 48->34KB,
// launch_bounds(64,5) -> 10 warps/SM.

#define THREADS 64
#define PTS     64
#define HID     128
#define NPTS    32768
#define BATCH   32
#define PARAMS_PER 50307
#define OMEGA0  30.0f

// pre-transposed hidden weights: [b][L][k*128+c]
__device__ float g_WT[BATCH * 3 * HID * HID];

__constant__ int c_woff[3] = {384, 16896, 33408};
__constant__ int c_boff[3] = {16768, 33280, 49792};

// ---- packed f32x2 helpers ----
__device__ __forceinline__ unsigned long long pack2f(float x, float y) {
    unsigned long long r;
    asm("mov.b64 %0, {%1,%2};" : "=l"(r)
        : "r"(__float_as_uint(x)), "r"(__float_as_uint(y)));
    return r;
}
__device__ __forceinline__ unsigned long long dup2f(float x) {
    unsigned long long r;
    asm("mov.b64 %0, {%1,%1};" : "=l"(r) : "r"(__float_as_uint(x)));
    return r;
}
__device__ __forceinline__ void unpack2f(unsigned long long v, float& x, float& y) {
    unsigned a, b;
    asm("mov.b64 {%0,%1}, %2;" : "=r"(a), "=r"(b) : "l"(v));
    x = __uint_as_float(a);
    y = __uint_as_float(b);
}
__device__ __forceinline__ unsigned long long ffma2(unsigned long long a,
                                                    unsigned long long b,
                                                    unsigned long long c) {
    unsigned long long d;
    asm("fma.rn.f32x2 %0, %1, %2, %3;" : "=l"(d) : "l"(a), "l"(b), "l"(c));
    return d;
}

// swizzled index into A (row stride 64 floats, float4-granular XOR swizzle)
__device__ __forceinline__ int aidx(int row, int m) {
    return (row << 6) + ((((m >> 2) ^ ((row >> 3) & 7)) << 2) | (m & 3));
}

// ---------------- pre-transpose kernel (unchanged) ----------------
__global__ __launch_bounds__(256)
void wtrans_kernel(const float* __restrict__ in0, const float* __restrict__ in1)
{
    __shared__ float t[32][33];
    const int tx = threadIdx.x;
    const int ty = threadIdx.y;
    const int ltid = ty * 32 + tx;

    const int in0_is_x = __syncthreads_or(fabsf(in0[ltid]) > 0.3f);
    const float* params = in0_is_x ? in1 : in0;

    const int mat = blockIdx.z;
    const int b = mat / 3, L = mat - 3 * b;
    const float* W = params + (size_t)b * PARAMS_PER + c_woff[L];
    const int k0 = blockIdx.x * 32;
    const int c0 = blockIdx.y * 32;

    #pragma unroll
    for (int i = 0; i < 32; i += 8)
        t[ty + i][tx] = W[(c0 + ty + i) * HID + k0 + tx];
    __syncthreads();

    float* O = g_WT + ((size_t)mat << 14);
    #pragma unroll
    for (int i = 0; i < 32; i += 8)
        O[(k0 + ty + i) * HID + c0 + tx] = t[tx][ty + i];
}

// ---------------- main fused kernel ----------------
__global__ __launch_bounds__(THREADS, 5)
void siren_fused_kernel(const float* __restrict__ in0,
                        const float* __restrict__ in1,
                        float* __restrict__ out)
{
    __shared__ float A[HID * PTS];   // 32 KB activations [k][m] swizzled
    __shared__ float SC[512];        // 2 KB scratch: W1+b1 / W5+b5

    const int tid = threadIdx.x;

    const int in0_is_x = __syncthreads_or(fabsf(in0[tid]) > 0.3f);
    const float* x      = in0_is_x ? in0 : in1;
    const float* params = in0_is_x ? in1 : in0;

    const int tx  = tid & 15;   // neuron groups: {4tx..4tx+3}, {64+4tx..+3}
    const int ty  = tid >> 4;   // 0..3: points 16ty..16ty+15
    const int b   = blockIdx.y;
    const int pt0 = blockIdx.x * PTS;
    const float* p = params + (size_t)b * PARAMS_PER;

    // ---- stage W1 (256) + b1 (128) ----
    for (int i = tid; i < 384; i += THREADS) SC[i] = p[i];
    __syncthreads();

    // ---- layer 1: 2 -> 128, sine; one point per thread ----
    {
        const int m = tid;
        float2 xv = ((const float2*)x)[(size_t)b * NPTS + pt0 + m];
        #pragma unroll 8
        for (int c = 0; c < HID; c++) {
            float z = fmaf(SC[2*c], xv.x, fmaf(SC[2*c + 1], xv.y, SC[256 + c]));
            A[aidx(c, m)] = __sinf(OMEGA0 * z);
        }
    }

    for (int L = 0; L < 3; L++) {
        const float4* Wl = (const float4*)(g_WT + (((size_t)b * 3 + L) << 14));
        const float* bg  = p + c_boff[L];

        // acc[j][ip]: neuron c_j, point pair (16ty+2ip, 16ty+2ip+1)
        unsigned long long acc[8][8];
        #pragma unroll
        for (int j = 0; j < 8; j++) {
            const int c = (j < 4) ? (4*tx + j) : (64 + 4*tx + (j - 4));
            unsigned long long bz = dup2f(__ldg(&bg[c]));
            #pragma unroll
            for (int i = 0; i < 8; i++) acc[j][i] = bz;
        }
        __syncthreads();   // A tile ready (layer1 write or prev write-back)

        for (int k8 = 0; k8 < 16; k8++) {
            const int key = k8 & 7;                 // (k>>3)&7
            const float4* Wk8 = Wl + (k8 << 8);     // 8 rows * 32 float4
            #pragma unroll
            for (int rr = 0; rr < 8; rr++) {
                const int k = k8 * 8 + rr;
                const float4* Ar = (const float4*)(A + (k << 6));
                float4 a0 = Ar[(4*ty + 0) ^ key];
                float4 a1 = Ar[(4*ty + 1) ^ key];
                float4 a2 = Ar[(4*ty + 2) ^ key];
                float4 a3 = Ar[(4*ty + 3) ^ key];
                float4 w0 = __ldg(Wk8 + (rr << 5) + tx);        // c=4tx..+3
                float4 w1 = __ldg(Wk8 + (rr << 5) + 16 + tx);   // c=64+4tx..+3
                unsigned long long ap[8];
                ap[0] = pack2f(a0.x, a0.y); ap[1] = pack2f(a0.z, a0.w);
                ap[2] = pack2f(a1.x, a1.y); ap[3] = pack2f(a1.z, a1.w);
                ap[4] = pack2f(a2.x, a2.y); ap[5] = pack2f(a2.z, a2.w);
                ap[6] = pack2f(a3.x, a3.y); ap[7] = pack2f(a3.z, a3.w);
                float wv[8] = {w0.x, w0.y, w0.z, w0.w,
                               w1.x, w1.y, w1.z, w1.w};
                #pragma unroll
                for (int j = 0; j < 8; j++) {
                    unsigned long long wd = dup2f(wv[j]);
                    #pragma unroll
                    for (int i = 0; i < 8; i++)
                        acc[j][i] = ffma2(ap[i], wd, acc[j][i]);
                }
            }
        }
        __syncthreads();   // all A reads done before overwrite

        // sine + write-back: neuron c_j row, 16 points = 4 float4 groups
        #pragma unroll
        for (int j = 0; j < 8; j++) {
            const int c = (j < 4) ? (4*tx + j) : (64 + 4*tx + (j - 4));
            float s[16];
            #pragma unroll
            for (int i = 0; i < 8; i++) {
                float z0, z1;
                unpack2f(acc[j][i], z0, z1);
                s[2*i]     = __sinf(OMEGA0 * z0);
                s[2*i + 1] = __sinf(OMEGA0 * z1);
            }
            const int keyc = (c >> 3) & 7;
            float4* Aw = (float4*)(A + (c << 6));
            Aw[(4*ty + 0) ^ keyc] = make_float4(s[0],  s[1],  s[2],  s[3]);
            Aw[(4*ty + 1) ^ keyc] = make_float4(s[4],  s[5],  s[6],  s[7]);
            Aw[(4*ty + 2) ^ keyc] = make_float4(s[8],  s[9],  s[10], s[11]);
            Aw[(4*ty + 3) ^ keyc] = make_float4(s[12], s[13], s[14], s[15]);
        }
    }
    __syncthreads();

    // ---- layer 5: 128 -> 3, linear ----
    for (int i = tid; i < 387; i += THREADS) SC[i] = p[49920 + i];
    __syncthreads();

    {
        const int m = tid;
        float acc0 = SC[384], acc1 = SC[385], acc2 = SC[386];
        #pragma unroll 4
        for (int k = 0; k < HID; k++) {
            float a = A[aidx(k, m)];
            acc0 = fmaf(SC[k],           a, acc0);
            acc1 = fmaf(SC[HID + k],     a, acc1);
            acc2 = fmaf(SC[2 * HID + k], a, acc2);
        }
        size_t o = ((size_t)b * NPTS + pt0 + m) * 3;
        out[o]     = acc0;
        out[o + 1] = acc1;
        out[o + 2] = acc2;
    }
}

extern "C" void kernel_launch(void* const* d_in, const int* in_sizes, int n_in,
                              void* d_out, int out_size)
{
    const float* in0 = (const float*)d_in[0];
    const float* in1 = (const float*)d_in[1];
    float* out = (float*)d_out;   // [32, 32768, 3]

    wtrans_kernel<<<dim3(4, 4, BATCH * 3), dim3(32, 8)>>>(in0, in1);

    dim3 grid(NPTS / PTS, BATCH);   // (512, 32)
    siren_fused_kernel<<<grid, THREADS>>>(in0, in1, out);
}

// round 11
// speedup vs baseline: 1.6190x; 1.6190x over previous
#include <cuda_runtime.h>

// SIREN fused inference, GB300 sm_103a — R11 (R10 design, build fixed:
// uint32_t -> unsigned int; no <cstdint> dependency).
// R9: weights must live in smem (per-k LDG thrashed L1 -> fma 32%).
// R8: synchronous staging cost ~0.5ms of fma-idle bubbles.
// R11: R8 GEMM + cp.async.cg double-buffered weight chunks — chunk kb+1
// streams while chunk kb computes. 50KB smem, 4 CTAs/SM.

#define THREADS 64
#define PTS     64
#define HID     128
#define NPTS    32768
#define BATCH   32
#define PARAMS_PER 50307
#define OMEGA0  30.0f
#define KCH     16   // k-rows per staged chunk (8 chunks, double-buffered)

// pre-transposed hidden weights: [b][L][k*128+c]
__device__ float g_WT[BATCH * 3 * HID * HID];

__constant__ int c_woff[3] = {384, 16896, 33408};
__constant__ int c_boff[3] = {16768, 33280, 49792};

// ---- packed f32x2 helpers ----
__device__ __forceinline__ unsigned long long pack2f(float x, float y) {
    unsigned long long r;
    asm("mov.b64 %0, {%1,%2};" : "=l"(r)
        : "r"(__float_as_uint(x)), "r"(__float_as_uint(y)));
    return r;
}
__device__ __forceinline__ unsigned long long dup2f(float x) {
    unsigned long long r;
    asm("mov.b64 %0, {%1,%1};" : "=l"(r) : "r"(__float_as_uint(x)));
    return r;
}
__device__ __forceinline__ void unpack2f(unsigned long long v, float& x, float& y) {
    unsigned a, b;
    asm("mov.b64 {%0,%1}, %2;" : "=r"(a), "=r"(b) : "l"(v));
    x = __uint_as_float(a);
    y = __uint_as_float(b);
}
__device__ __forceinline__ unsigned long long ffma2(unsigned long long a,
                                                    unsigned long long b,
                                                    unsigned long long c) {
    unsigned long long d;
    asm("fma.rn.f32x2 %0, %1, %2, %3;" : "=l"(d) : "l"(a), "l"(b), "l"(c));
    return d;
}

// ---- cp.async helpers ----
__device__ __forceinline__ void cp16(unsigned int dst_smem, const void* src) {
    asm volatile("cp.async.cg.shared.global [%0], [%1], 16;"
                 :: "r"(dst_smem), "l"(src));
}
__device__ __forceinline__ void cp_commit() {
    asm volatile("cp.async.commit_group;");
}
__device__ __forceinline__ void cp_wait0() {
    asm volatile("cp.async.wait_group 0;");
}

// swizzled index into A (row stride 64 floats, float4-granular XOR swizzle)
__device__ __forceinline__ int aidx(int row, int m) {
    return (row << 6) + ((((m >> 2) ^ ((row >> 3) & 7)) << 2) | (m & 3));
}

// ---------------- pre-transpose kernel (unchanged) ----------------
__global__ __launch_bounds__(256)
void wtrans_kernel(const float* __restrict__ in0, const float* __restrict__ in1)
{
    __shared__ float t[32][33];
    const int tx = threadIdx.x;
    const int ty = threadIdx.y;
    const int ltid = ty * 32 + tx;

    const int in0_is_x = __syncthreads_or(fabsf(in0[ltid]) > 0.3f);
    const float* params = in0_is_x ? in1 : in0;

    const int mat = blockIdx.z;
    const int b = mat / 3, L = mat - 3 * b;
    const float* W = params + (size_t)b * PARAMS_PER + c_woff[L];
    const int k0 = blockIdx.x * 32;
    const int c0 = blockIdx.y * 32;

    #pragma unroll
    for (int i = 0; i < 32; i += 8)
        t[ty + i][tx] = W[(c0 + ty + i) * HID + k0 + tx];
    __syncthreads();

    float* O = g_WT + ((size_t)mat << 14);
    #pragma unroll
    for (int i = 0; i < 32; i += 8)
        O[(k0 + ty + i) * HID + c0 + tx] = t[tx][ty + i];
}

// ---------------- main fused kernel ----------------
__global__ __launch_bounds__(THREADS, 4)
void siren_fused_kernel(const float* __restrict__ in0,
                        const float* __restrict__ in1,
                        float* __restrict__ out)
{
    __shared__ float A[HID * PTS];           // 32 KB activations, swizzled
    __shared__ float WS[2][KCH * HID];       // 2 x 8 KB weight chunks
    __shared__ float SC[512];                // scratch: W1+b1 / W5+b5

    const int tid = threadIdx.x;

    const int in0_is_x = __syncthreads_or(fabsf(in0[tid]) > 0.3f);
    const float* x      = in0_is_x ? in0 : in1;
    const float* params = in0_is_x ? in1 : in0;

    const int tx  = tid & 15;   // neuron groups: {4tx..4tx+3}, {64+4tx..+3}
    const int ty  = tid >> 4;   // 0..3: points 16ty..16ty+15
    const int b   = blockIdx.y;
    const int pt0 = blockIdx.x * PTS;
    const float* p = params + (size_t)b * PARAMS_PER;

    // ---- stage W1 (256) + b1 (128) ----
    for (int i = tid; i < 384; i += THREADS) SC[i] = p[i];
    __syncthreads();

    // ---- layer 1: 2 -> 128, sine; one point per thread ----
    {
        const int m = tid;
        float2 xv = ((const float2*)x)[(size_t)b * NPTS + pt0 + m];
        #pragma unroll 8
        for (int c = 0; c < HID; c++) {
            float z = fmaf(SC[2*c], xv.x, fmaf(SC[2*c + 1], xv.y, SC[256 + c]));
            A[aidx(c, m)] = __sinf(OMEGA0 * z);
        }
    }

    for (int L = 0; L < 3; L++) {
        const float* WTl = g_WT + (((size_t)b * 3 + L) << 14);
        const float* bg  = p + c_boff[L];

        // prologue: async-copy chunk 0 into buffer 0 (KCH*128 floats = 512 f4)
        {
            unsigned int dst = (unsigned int)__cvta_generic_to_shared(WS[0]);
            const float4* src = (const float4*)WTl;
            #pragma unroll
            for (int it = 0; it < (KCH * HID / 4) / THREADS; it++)
                cp16(dst + (tid + THREADS * it) * 16, src + tid + THREADS * it);
            cp_commit();
        }

        // acc[j][ip]: neuron c_j, point pair (16ty+2ip, 16ty+2ip+1)
        unsigned long long acc[8][8];
        #pragma unroll
        for (int j = 0; j < 8; j++) {
            const int c = (j < 4) ? (4*tx + j) : (64 + 4*tx + (j - 4));
            unsigned long long bz = dup2f(__ldg(&bg[c]));
            #pragma unroll
            for (int i = 0; i < 8; i++) acc[j][i] = bz;
        }
        __syncthreads();   // A tile ready (layer1 write or prev write-back)

        for (int kb = 0; kb < HID / KCH; kb++) {
            cp_wait0();
            __syncthreads();   // chunk kb visible; buf[(kb+1)&1] fully consumed

            if (kb + 1 < HID / KCH) {
                unsigned int dst =
                    (unsigned int)__cvta_generic_to_shared(WS[(kb + 1) & 1]);
                const float4* src = (const float4*)(WTl + (kb + 1) * KCH * HID);
                #pragma unroll
                for (int it = 0; it < (KCH * HID / 4) / THREADS; it++)
                    cp16(dst + (tid + THREADS * it) * 16, src + tid + THREADS * it);
                cp_commit();
            }

            const float* WSb = WS[kb & 1];
            #pragma unroll
            for (int r8 = 0; r8 < KCH / 8; r8++) {
                const int key = (kb * (KCH / 8) + r8) & 7;   // (k>>3)&7
                #pragma unroll
                for (int rr = 0; rr < 8; rr++) {
                    const int r = r8 * 8 + rr;
                    const int k = kb * KCH + r;
                    const float4* Ar = (const float4*)(A + (k << 6));
                    float4 a0 = Ar[(4*ty + 0) ^ key];
                    float4 a1 = Ar[(4*ty + 1) ^ key];
                    float4 a2 = Ar[(4*ty + 2) ^ key];
                    float4 a3 = Ar[(4*ty + 3) ^ key];
                    const float4* Wr = (const float4*)(WSb + (r << 7));
                    float4 w0 = Wr[tx];        // c = 4tx..4tx+3
                    float4 w1 = Wr[16 + tx];   // c = 64+4tx..+3
                    unsigned long long ap[8];
                    ap[0] = pack2f(a0.x, a0.y); ap[1] = pack2f(a0.z, a0.w);
                    ap[2] = pack2f(a1.x, a1.y); ap[3] = pack2f(a1.z, a1.w);
                    ap[4] = pack2f(a2.x, a2.y); ap[5] = pack2f(a2.z, a2.w);
                    ap[6] = pack2f(a3.x, a3.y); ap[7] = pack2f(a3.z, a3.w);
                    float wv[8] = {w0.x, w0.y, w0.z, w0.w,
                                   w1.x, w1.y, w1.z, w1.w};
                    #pragma unroll
                    for (int j = 0; j < 8; j++) {
                        unsigned long long wd = dup2f(wv[j]);
                        #pragma unroll
                        for (int i = 0; i < 8; i++)
                            acc[j][i] = ffma2(ap[i], wd, acc[j][i]);
                    }
                }
            }
        }
        __syncthreads();   // all A reads done before overwrite

        // sine + write-back: neuron c_j row, 16 points = 4 float4 groups
        #pragma unroll
        for (int j = 0; j < 8; j++) {
            const int c = (j < 4) ? (4*tx + j) : (64 + 4*tx + (j - 4));
            float s[16];
            #pragma unroll
            for (int i = 0; i < 8; i++) {
                float z0, z1;
                unpack2f(acc[j][i], z0, z1);
                s[2*i]     = __sinf(OMEGA0 * z0);
                s[2*i + 1] = __sinf(OMEGA0 * z1);
            }
            const int keyc = (c >> 3) & 7;
            float4* Aw = (float4*)(A + (c << 6));
            Aw[(4*ty + 0) ^ keyc] = make_float4(s[0],  s[1],  s[2],  s[3]);
            Aw[(4*ty + 1) ^ keyc] = make_float4(s[4],  s[5],  s[6],  s[7]);
            Aw[(4*ty + 2) ^ keyc] = make_float4(s[8],  s[9],  s[10], s[11]);
            Aw[(4*ty + 3) ^ keyc] = make_float4(s[12], s[13], s[14], s[15]);
        }
    }
    __syncthreads();

    // ---- layer 5: 128 -> 3, linear ----
    for (int i = tid; i < 387; i += THREADS) SC[i] = p[49920 + i];
    __syncthreads();

    {
        const int m = tid;
        float acc0 = SC[384], acc1 = SC[385], acc2 = SC[386];
        #pragma unroll 4
        for (int k = 0; k < HID; k++) {
            float a = A[aidx(k, m)];
            acc0 = fmaf(SC[k],           a, acc0);
            acc1 = fmaf(SC[HID + k],     a, acc1);
            acc2 = fmaf(SC[2 * HID + k], a, acc2);
        }
        size_t o = ((size_t)b * NPTS + pt0 + m) * 3;
        out[o]     = acc0;
        out[o + 1] = acc1;
        out[o + 2] = acc2;
    }
}

extern "C" void kernel_launch(void* const* d_in, const int* in_sizes, int n_in,
                              void* d_out, int out_size)
{
    const float* in0 = (const float*)d_in[0];
    const float* in1 = (const float*)d_in[1];
    float* out = (float*)d_out;   // [32, 32768, 3]

    wtrans_kernel<<<dim3(4, 4, BATCH * 3), dim3(32, 8)>>>(in0, in1);

    dim3 grid(NPTS / PTS, BATCH);   // (512, 32)
    siren_fused_kernel<<<grid, THREADS>>>(in0, in1, out);
}

// round 13
// speedup vs baseline: 3.5425x; 2.1881x over previous
#include <cuda_runtime.h>
#include <cuda_fp16.h>

// SIREN fused inference, GB300 sm_103a — R13: warp-level split-fp16 HMMA.
// R12 found ptxas (compute_103 target) rejects tcgen05; mma.sync/ldmatrix/
// cp.async are available. Path: act/W split fp16 hi+lo (3 products into one
// fp32 accumulator, ~22-bit effective), activations live entirely in
// registers (C-frag of layer L == A-frag of layer L+1), W streamed as
// ldmatrix-native blocks via double-buffered cp.async.

#define THREADS 256
#define PTS     128
#define HID     128
#define NPTS    32768
#define BATCH   32
#define PARAMS_PER 50307
#define OMEGA0  30.0f

// pre-split fp16 weights, ldmatrix-block layout:
// per mat(96): 4 chunks(k32) x [hi 8KB | lo 8KB]; block addr (halves):
// kc*8192 + sel*4096 + ((ks*16+nt)*2+kb)*64 + r*8 + (k&7)
__device__ __half g_Wh[96 * 32768];

__constant__ int c_woff[3] = {384, 16896, 33408};

__device__ __forceinline__ unsigned smem_u32(const void* p) {
    return (unsigned)__cvta_generic_to_shared(p);
}
__device__ __forceinline__ void cp16(unsigned dst, const void* src) {
    asm volatile("cp.async.cg.shared.global [%0], [%1], 16;" :: "r"(dst), "l"(src));
}
__device__ __forceinline__ void cp_commit() { asm volatile("cp.async.commit_group;"); }
__device__ __forceinline__ void cp_wait0()  { asm volatile("cp.async.wait_group 0;"); }

__device__ __forceinline__ void ldsm2(unsigned& r0, unsigned& r1, unsigned addr) {
    asm volatile("ldmatrix.sync.aligned.m8n8.x2.shared.b16 {%0,%1}, [%2];"
                 : "=r"(r0), "=r"(r1) : "r"(addr));
}
__device__ __forceinline__ void mma16816(float* c, const unsigned* a,
                                         unsigned b0, unsigned b1) {
    asm volatile("mma.sync.aligned.m16n8k16.row.col.f32.f16.f16.f32 "
                 "{%0,%1,%2,%3}, {%4,%5,%6,%7}, {%8,%9}, {%0,%1,%2,%3};"
                 : "+f"(c[0]), "+f"(c[1]), "+f"(c[2]), "+f"(c[3])
                 : "r"(a[0]), "r"(a[1]), "r"(a[2]), "r"(a[3]), "r"(b0), "r"(b1));
}

// sine -> split fp16 hi/lo, packed as half2 (first arg in low half)
__device__ __forceinline__ void sin_split2(float z0, float z1,
                                           unsigned& hi, unsigned& lo) {
    float s0 = __sinf(OMEGA0 * z0), s1 = __sinf(OMEGA0 * z1);
    __half h0 = __float2half_rn(s0), h1 = __float2half_rn(s1);
    __half2 hp = __halves2half2(h0, h1);
    __half2 lp = __floats2half2_rn(s0 - __half2float(h0), s1 - __half2float(h1));
    hi = *(unsigned*)&hp;
    lo = *(unsigned*)&lp;
}

// ---------------- pre-pass: split W into fp16 hi/lo ldmatrix blocks --------
__global__ __launch_bounds__(256)
void wprep_kernel(const float* __restrict__ in0, const float* __restrict__ in1)
{
    const int t = threadIdx.x;
    const int in0_is_x = __syncthreads_or(fabsf(in0[t]) > 0.3f);
    const float* params = in0_is_x ? in1 : in0;

    const int mat = blockIdx.x;              // 0..95
    const int b = mat / 3, L = mat - 3 * b;
    const float* W = params + (size_t)b * PARAMS_PER + c_woff[L];  // [c][k]
    __half* dst = g_Wh + (size_t)mat * 32768;

    for (int i = 0; i < 64; i++) {
        int idx = t + 256 * i;               // c*128 + k
        int c = idx >> 7, k = idx & 127;
        float w = W[idx];
        __half h = __float2half_rn(w);
        __half l = __float2half_rn(w - __half2float(h));
        int kc = k >> 5, ks = (k >> 4) & 1, kb = (k >> 3) & 1;
        int nt = c >> 3, r = c & 7;
        int off = kc * 8192 + ((ks * 16 + nt) * 2 + kb) * 64 + r * 8 + (k & 7);
        dst[off]        = h;      // sel 0 (hi)
        dst[off + 4096] = l;      // sel 1 (lo)
    }
}

// ---------------- main fused tensor kernel ----------------
__global__ __launch_bounds__(THREADS, 1)
void siren_mma_kernel(const float* __restrict__ in0,
                      const float* __restrict__ in1,
                      float* __restrict__ out)
{
    __shared__ __align__(1024) __half WB[2][8192];   // 2 x 16KB chunk buffers
    __shared__ float SC[1184];                        // W1,b1,b2,b3,b4,W5,b5

    const int tid  = threadIdx.x;
    const int wid  = tid >> 5;
    const int lane = tid & 31;
    const int g    = lane >> 2;   // point row within warp tile
    const int t    = lane & 3;

    const int in0_is_x = __syncthreads_or(fabsf(in0[tid]) > 0.3f);
    const float* x      = in0_is_x ? in0 : in1;
    const float* params = in0_is_x ? in1 : in0;

    const int b   = blockIdx.y;
    const int pt0 = blockIdx.x * PTS;
    const float* p = params + (size_t)b * PARAMS_PER;
    const unsigned wbS = smem_u32(WB);

    // kick chunk 0 (layer 0) immediately
    {
        const float4* src = (const float4*)(g_Wh + (size_t)(b * 3) * 32768);
        #pragma unroll
        for (int it = 0; it < 4; it++)
            cp16(wbS + (tid + 256 * it) * 16, src + tid + 256 * it);
        cp_commit();
    }

    // stage scalars: [0:256) W1, [256:384) b1, [384:512) b2, [512:640) b3,
    // [640:768) b4, [768:1152) W5, [1152:1155) b5
    for (int i = tid; i < 1155; i += THREADS) {
        int gidx;
        if      (i < 384)  gidx = i;
        else if (i < 512)  gidx = 16768 + (i - 384);
        else if (i < 640)  gidx = 33280 + (i - 512);
        else if (i < 768)  gidx = 49792 + (i - 640);
        else if (i < 1152) gidx = 49920 + (i - 768);
        else               gidx = 50304 + (i - 1152);
        SC[i] = p[gidx];
    }
    __syncthreads();

    // ---- layer 1: build A fragments (hi/lo fp16) directly in registers ----
    unsigned ah[8][4], al[8][4];
    {
        const int m0 = pt0 + wid * 16 + g;
        float2 x0 = ((const float2*)x)[(size_t)b * NPTS + m0];
        float2 x1 = ((const float2*)x)[(size_t)b * NPTS + m0 + 8];
        #pragma unroll
        for (int kt = 0; kt < 8; kt++) {
            const int c0 = kt * 16 + 2 * t;
            const int c2 = c0 + 8;
            float za0 = fmaf(SC[2*c0],   x0.x, fmaf(SC[2*c0+1],   x0.y, SC[256+c0]));
            float za1 = fmaf(SC[2*c0+2], x0.x, fmaf(SC[2*c0+3],   x0.y, SC[256+c0+1]));
            float zb0 = fmaf(SC[2*c0],   x1.x, fmaf(SC[2*c0+1],   x1.y, SC[256+c0]));
            float zb1 = fmaf(SC[2*c0+2], x1.x, fmaf(SC[2*c0+3],   x1.y, SC[256+c0+1]));
            float zc0 = fmaf(SC[2*c2],   x0.x, fmaf(SC[2*c2+1],   x0.y, SC[256+c2]));
            float zc1 = fmaf(SC[2*c2+2], x0.x, fmaf(SC[2*c2+3],   x0.y, SC[256+c2+1]));
            float zd0 = fmaf(SC[2*c2],   x1.x, fmaf(SC[2*c2+1],   x1.y, SC[256+c2]));
            float zd1 = fmaf(SC[2*c2+2], x1.x, fmaf(SC[2*c2+3],   x1.y, SC[256+c2+1]));
            sin_split2(za0, za1, ah[kt][0], al[kt][0]);
            sin_split2(zb0, zb1, ah[kt][1], al[kt][1]);
            sin_split2(zc0, zc1, ah[kt][2], al[kt][2]);
            sin_split2(zd0, zd1, ah[kt][3], al[kt][3]);
        }
    }

    const unsigned lpart = (unsigned)((lane & 15) << 4);

    for (int L = 0; L < 3; L++) {
        // accumulators init = bias (c0/c1 row g, c2/c3 row g+8 share bias[n])
        float acc[16][4];
        #pragma unroll
        for (int nt = 0; nt < 16; nt++) {
            float b0 = SC[384 + L * 128 + nt * 8 + 2 * t];
            float b1 = SC[384 + L * 128 + nt * 8 + 2 * t + 1];
            acc[nt][0] = b0; acc[nt][1] = b1; acc[nt][2] = b0; acc[nt][3] = b1;
        }

        #pragma unroll
        for (int kc = 0; kc < 4; kc++) {
            const int q = L * 4 + kc;
            cp_wait0();
            __syncthreads();
            if (q < 11) {   // issue next chunk into the other buffer
                const int qn = q + 1;
                const float4* src = (const float4*)(g_Wh
                    + (size_t)(b * 3 + (qn >> 2)) * 32768 + (size_t)(qn & 3) * 8192);
                unsigned dst = wbS + ((unsigned)(qn & 1) << 14);
                #pragma unroll
                for (int it = 0; it < 4; it++)
                    cp16(dst + (tid + 256 * it) * 16, src + tid + 256 * it);
                cp_commit();
            }

            const unsigned base = wbS + ((unsigned)(q & 1) << 14) + lpart;
            #pragma unroll
            for (int ks = 0; ks < 2; ks++) {
                const int kst = kc * 2 + ks;
                #pragma unroll
                for (int nt = 0; nt < 16; nt++) {
                    unsigned off = base + (unsigned)((ks * 16 + nt) * 256);
                    unsigned bh0, bh1, bl0, bl1;
                    ldsm2(bh0, bh1, off);
                    ldsm2(bl0, bl1, off + 8192);
                    mma16816(acc[nt], ah[kst], bh0, bh1);   // ah*wh
                    mma16816(acc[nt], al[kst], bh0, bh1);   // al*wh
                    mma16816(acc[nt], ah[kst], bl0, bl1);   // ah*wl
                }
            }
        }

        if (L < 2) {
            // epilogue: sine + split; C frags become next layer's A frags
            #pragma unroll
            for (int kt = 0; kt < 8; kt++) {
                sin_split2(acc[2*kt][0],   acc[2*kt][1],   ah[kt][0], al[kt][0]);
                sin_split2(acc[2*kt][2],   acc[2*kt][3],   ah[kt][1], al[kt][1]);
                sin_split2(acc[2*kt+1][0], acc[2*kt+1][1], ah[kt][2], al[kt][2]);
                sin_split2(acc[2*kt+1][2], acc[2*kt+1][3], ah[kt][3], al[kt][3]);
            }
        } else {
            // final: sine(layer4) fused with layer5 (128->3) via quad shuffles
            float p00 = 0.f, p01 = 0.f, p02 = 0.f;   // point row g
            float p10 = 0.f, p11 = 0.f, p12 = 0.f;   // point row g+8
            #pragma unroll
            for (int nt = 0; nt < 16; nt++) {
                const int c0 = nt * 8 + 2 * t;
                const int c1 = c0 + 1;
                float s0 = __sinf(OMEGA0 * acc[nt][0]);
                float s1 = __sinf(OMEGA0 * acc[nt][1]);
                float s2 = __sinf(OMEGA0 * acc[nt][2]);
                float s3 = __sinf(OMEGA0 * acc[nt][3]);
                p00 = fmaf(SC[768 + c0],       s0, fmaf(SC[768 + c1],       s1, p00));
                p01 = fmaf(SC[768 + 128 + c0], s0, fmaf(SC[768 + 128 + c1], s1, p01));
                p02 = fmaf(SC[768 + 256 + c0], s0, fmaf(SC[768 + 256 + c1], s1, p02));
                p10 = fmaf(SC[768 + c0],       s2, fmaf(SC[768 + c1],       s3, p10));
                p11 = fmaf(SC[768 + 128 + c0], s2, fmaf(SC[768 + 128 + c1], s3, p11));
                p12 = fmaf(SC[768 + 256 + c0], s2, fmaf(SC[768 + 256 + c1], s3, p12));
            }
            #pragma unroll
            for (int d = 1; d <= 2; d <<= 1) {
                p00 += __shfl_xor_sync(0xFFFFFFFF, p00, d);
                p01 += __shfl_xor_sync(0xFFFFFFFF, p01, d);
                p02 += __shfl_xor_sync(0xFFFFFFFF, p02, d);
                p10 += __shfl_xor_sync(0xFFFFFFFF, p10, d);
                p11 += __shfl_xor_sync(0xFFFFFFFF, p11, d);
                p12 += __shfl_xor_sync(0xFFFFFFFF, p12, d);
            }
            if (t == 0) {
                const int m0 = pt0 + wid * 16 + g;
                size_t o0 = ((size_t)b * NPTS + m0) * 3;
                size_t o1 = ((size_t)b * NPTS + m0 + 8) * 3;
                out[o0]     = p00 + SC[1152];
                out[o0 + 1] = p01 + SC[1153];
                out[o0 + 2] = p02 + SC[1154];
                out[o1]     = p10 + SC[1152];
                out[o1 + 1] = p11 + SC[1153];
                out[o1 + 2] = p12 + SC[1154];
            }
        }
    }
}

extern "C" void kernel_launch(void* const* d_in, const int* in_sizes, int n_in,
                              void* d_out, int out_size)
{
    const float* in0 = (const float*)d_in[0];
    const float* in1 = (const float*)d_in[1];
    float* out = (float*)d_out;   // [32, 32768, 3]

    wprep_kernel<<<BATCH * 3, 256>>>(in0, in1);

    dim3 grid(NPTS / PTS, BATCH);   // (256, 32)
    siren_mma_kernel<<<grid, THREADS>>>(in0, in1, out);
}

// round 14
// speedup vs baseline: 3.8674x; 1.0917x over previous
#include <cuda_runtime.h>
#include <cuda_fp16.h>

// SIREN fused inference, GB300 sm_103a — R14.
// R13 (842us): tensor 59%, occ 12.4% (1 CTA/SM) — per-layer epilogues
// serialize against MMA with nothing to fill the gap. R14 halves the CTA
// (128 threads, 64-pt tile) so 2 CTAs/SM co-reside in staggered phases:
// one CTA's sine/split epilogue overlaps the other's MMA bursts.
// Warp tile, weight layout, and math identical to R13.

#define THREADS 128
#define PTS     64
#define HID     128
#define NPTS    32768
#define BATCH   32
#define PARAMS_PER 50307
#define OMEGA0  30.0f

// pre-split fp16 weights, ldmatrix-block layout:
// per mat(96): 4 chunks(k32) x [hi 8KB | lo 8KB]; block addr (halves):
// kc*8192 + sel*4096 + ((ks*16+nt)*2+kb)*64 + r*8 + (k&7)
__device__ __half g_Wh[96 * 32768];

__constant__ int c_woff[3] = {384, 16896, 33408};

__device__ __forceinline__ unsigned smem_u32(const void* p) {
    return (unsigned)__cvta_generic_to_shared(p);
}
__device__ __forceinline__ void cp16(unsigned dst, const void* src) {
    asm volatile("cp.async.cg.shared.global [%0], [%1], 16;" :: "r"(dst), "l"(src));
}
__device__ __forceinline__ void cp_commit() { asm volatile("cp.async.commit_group;"); }
__device__ __forceinline__ void cp_wait0()  { asm volatile("cp.async.wait_group 0;"); }

__device__ __forceinline__ void ldsm2(unsigned& r0, unsigned& r1, unsigned addr) {
    asm volatile("ldmatrix.sync.aligned.m8n8.x2.shared.b16 {%0,%1}, [%2];"
                 : "=r"(r0), "=r"(r1) : "r"(addr));
}
__device__ __forceinline__ void mma16816(float* c, const unsigned* a,
                                         unsigned b0, unsigned b1) {
    asm volatile("mma.sync.aligned.m16n8k16.row.col.f32.f16.f16.f32 "
                 "{%0,%1,%2,%3}, {%4,%5,%6,%7}, {%8,%9}, {%0,%1,%2,%3};"
                 : "+f"(c[0]), "+f"(c[1]), "+f"(c[2]), "+f"(c[3])
                 : "r"(a[0]), "r"(a[1]), "r"(a[2]), "r"(a[3]), "r"(b0), "r"(b1));
}

// sine -> split fp16 hi/lo, packed as half2 (first arg in low half)
__device__ __forceinline__ void sin_split2(float z0, float z1,
                                           unsigned& hi, unsigned& lo) {
    float s0 = __sinf(OMEGA0 * z0), s1 = __sinf(OMEGA0 * z1);
    __half h0 = __float2half_rn(s0), h1 = __float2half_rn(s1);
    __half2 hp = __halves2half2(h0, h1);
    __half2 lp = __floats2half2_rn(s0 - __half2float(h0), s1 - __half2float(h1));
    hi = *(unsigned*)&hp;
    lo = *(unsigned*)&lp;
}

// ---------------- pre-pass: split W into fp16 hi/lo ldmatrix blocks --------
__global__ __launch_bounds__(256)
void wprep_kernel(const float* __restrict__ in0, const float* __restrict__ in1)
{
    const int t = threadIdx.x;
    const int in0_is_x = __syncthreads_or(fabsf(in0[t]) > 0.3f);
    const float* params = in0_is_x ? in1 : in0;

    const int mat = blockIdx.x;              // 0..95
    const int b = mat / 3, L = mat - 3 * b;
    const float* W = params + (size_t)b * PARAMS_PER + c_woff[L];  // [c][k]
    __half* dst = g_Wh + (size_t)mat * 32768;

    for (int i = 0; i < 64; i++) {
        int idx = t + 256 * i;               // c*128 + k
        int c = idx >> 7, k = idx & 127;
        float w = W[idx];
        __half h = __float2half_rn(w);
        __half l = __float2half_rn(w - __half2float(h));
        int kc = k >> 5, ks = (k >> 4) & 1, kb = (k >> 3) & 1;
        int nt = c >> 3, r = c & 7;
        int off = kc * 8192 + ((ks * 16 + nt) * 2 + kb) * 64 + r * 8 + (k & 7);
        dst[off]        = h;      // sel 0 (hi)
        dst[off + 4096] = l;      // sel 1 (lo)
    }
}

// ---------------- main fused tensor kernel ----------------
__global__ __launch_bounds__(THREADS, 2)
void siren_mma_kernel(const float* __restrict__ in0,
                      const float* __restrict__ in1,
                      float* __restrict__ out)
{
    __shared__ __align__(1024) __half WB[2][8192];   // 2 x 16KB chunk buffers
    __shared__ float SC[1184];                        // W1,b1,b2,b3,b4,W5,b5

    const int tid  = threadIdx.x;
    const int wid  = tid >> 5;    // 0..3
    const int lane = tid & 31;
    const int g    = lane >> 2;   // point row within warp tile
    const int t    = lane & 3;

    const int in0_is_x = __syncthreads_or(fabsf(in0[tid]) > 0.3f);
    const float* x      = in0_is_x ? in0 : in1;
    const float* params = in0_is_x ? in1 : in0;

    const int b   = blockIdx.y;
    const int pt0 = blockIdx.x * PTS;
    const float* p = params + (size_t)b * PARAMS_PER;
    const unsigned wbS = smem_u32(WB);

    // kick chunk 0 (layer 0) immediately: 16KB = 1024 float4, 8/thread
    {
        const float4* src = (const float4*)(g_Wh + (size_t)(b * 3) * 32768);
        #pragma unroll
        for (int it = 0; it < 8; it++)
            cp16(wbS + (tid + THREADS * it) * 16, src + tid + THREADS * it);
        cp_commit();
    }

    // stage scalars: [0:256) W1, [256:384) b1, [384:512) b2, [512:640) b3,
    // [640:768) b4, [768:1152) W5, [1152:1155) b5
    for (int i = tid; i < 1155; i += THREADS) {
        int gidx;
        if      (i < 384)  gidx = i;
        else if (i < 512)  gidx = 16768 + (i - 384);
        else if (i < 640)  gidx = 33280 + (i - 512);
        else if (i < 768)  gidx = 49792 + (i - 640);
        else if (i < 1152) gidx = 49920 + (i - 768);
        else               gidx = 50304 + (i - 1152);
        SC[i] = p[gidx];
    }
    __syncthreads();

    // ---- layer 1: build A fragments (hi/lo fp16) directly in registers ----
    unsigned ah[8][4], al[8][4];
    {
        const int m0 = pt0 + wid * 16 + g;
        float2 x0 = ((const float2*)x)[(size_t)b * NPTS + m0];
        float2 x1 = ((const float2*)x)[(size_t)b * NPTS + m0 + 8];
        #pragma unroll
        for (int kt = 0; kt < 8; kt++) {
            const int c0 = kt * 16 + 2 * t;
            const int c2 = c0 + 8;
            float za0 = fmaf(SC[2*c0],   x0.x, fmaf(SC[2*c0+1],   x0.y, SC[256+c0]));
            float za1 = fmaf(SC[2*c0+2], x0.x, fmaf(SC[2*c0+3],   x0.y, SC[256+c0+1]));
            float zb0 = fmaf(SC[2*c0],   x1.x, fmaf(SC[2*c0+1],   x1.y, SC[256+c0]));
            float zb1 = fmaf(SC[2*c0+2], x1.x, fmaf(SC[2*c0+3],   x1.y, SC[256+c0+1]));
            float zc0 = fmaf(SC[2*c2],   x0.x, fmaf(SC[2*c2+1],   x0.y, SC[256+c2]));
            float zc1 = fmaf(SC[2*c2+2], x0.x, fmaf(SC[2*c2+3],   x0.y, SC[256+c2+1]));
            float zd0 = fmaf(SC[2*c2],   x1.x, fmaf(SC[2*c2+1],   x1.y, SC[256+c2]));
            float zd1 = fmaf(SC[2*c2+2], x1.x, fmaf(SC[2*c2+3],   x1.y, SC[256+c2+1]));
            sin_split2(za0, za1, ah[kt][0], al[kt][0]);
            sin_split2(zb0, zb1, ah[kt][1], al[kt][1]);
            sin_split2(zc0, zc1, ah[kt][2], al[kt][2]);
            sin_split2(zd0, zd1, ah[kt][3], al[kt][3]);
        }
    }

    const unsigned lpart = (unsigned)((lane & 15) << 4);

    for (int L = 0; L < 3; L++) {
        // accumulators init = bias
        float acc[16][4];
        #pragma unroll
        for (int nt = 0; nt < 16; nt++) {
            float b0 = SC[384 + L * 128 + nt * 8 + 2 * t];
            float b1 = SC[384 + L * 128 + nt * 8 + 2 * t + 1];
            acc[nt][0] = b0; acc[nt][1] = b1; acc[nt][2] = b0; acc[nt][3] = b1;
        }

        #pragma unroll
        for (int kc = 0; kc < 4; kc++) {
            const int q = L * 4 + kc;
            cp_wait0();
            __syncthreads();
            if (q < 11) {   // issue next chunk into the other buffer
                const int qn = q + 1;
                const float4* src = (const float4*)(g_Wh
                    + (size_t)(b * 3 + (qn >> 2)) * 32768 + (size_t)(qn & 3) * 8192);
                unsigned dst = wbS + ((unsigned)(qn & 1) << 14);
                #pragma unroll
                for (int it = 0; it < 8; it++)
                    cp16(dst + (tid + THREADS * it) * 16, src + tid + THREADS * it);
                cp_commit();
            }

            const unsigned base = wbS + ((unsigned)(q & 1) << 14) + lpart;
            #pragma unroll
            for (int ks = 0; ks < 2; ks++) {
                const int kst = kc * 2 + ks;
                #pragma unroll
                for (int nt = 0; nt < 16; nt++) {
                    unsigned off = base + (unsigned)((ks * 16 + nt) * 256);
                    unsigned bh0, bh1, bl0, bl1;
                    ldsm2(bh0, bh1, off);
                    ldsm2(bl0, bl1, off + 8192);
                    mma16816(acc[nt], ah[kst], bh0, bh1);   // ah*wh
                    mma16816(acc[nt], al[kst], bh0, bh1);   // al*wh
                    mma16816(acc[nt], ah[kst], bl0, bl1);   // ah*wl
                }
            }
        }

        if (L < 2) {
            // epilogue: sine + split; C frags become next layer's A frags
            #pragma unroll
            for (int kt = 0; kt < 8; kt++) {
                sin_split2(acc[2*kt][0],   acc[2*kt][1],   ah[kt][0], al[kt][0]);
                sin_split2(acc[2*kt][2],   acc[2*kt][3],   ah[kt][1], al[kt][1]);
                sin_split2(acc[2*kt+1][0], acc[2*kt+1][1], ah[kt][2], al[kt][2]);
                sin_split2(acc[2*kt+1][2], acc[2*kt+1][3], ah[kt][3], al[kt][3]);
            }
        } else {
            // final: sine(layer4) fused with layer5 (128->3) via quad shuffles
            float p00 = 0.f, p01 = 0.f, p02 = 0.f;   // point row g
            float p10 = 0.f, p11 = 0.f, p12 = 0.f;   // point row g+8
            #pragma unroll
            for (int nt = 0; nt < 16; nt++) {
                const int c0 = nt * 8 + 2 * t;
                const int c1 = c0 + 1;
                float s0 = __sinf(OMEGA0 * acc[nt][0]);
                float s1 = __sinf(OMEGA0 * acc[nt][1]);
                float s2 = __sinf(OMEGA0 * acc[nt][2]);
                float s3 = __sinf(OMEGA0 * acc[nt][3]);
                p00 = fmaf(SC[768 + c0],       s0, fmaf(SC[768 + c1],       s1, p00));
                p01 = fmaf(SC[768 + 128 + c0], s0, fmaf(SC[768 + 128 + c1], s1, p01));
                p02 = fmaf(SC[768 + 256 + c0], s0, fmaf(SC[768 + 256 + c1], s1, p02));
                p10 = fmaf(SC[768 + c0],       s2, fmaf(SC[768 + c1],       s3, p10));
                p11 = fmaf(SC[768 + 128 + c0], s2, fmaf(SC[768 + 128 + c1], s3, p11));
                p12 = fmaf(SC[768 + 256 + c0], s2, fmaf(SC[768 + 256 + c1], s3, p12));
            }
            #pragma unroll
            for (int d = 1; d <= 2; d <<= 1) {
                p00 += __shfl_xor_sync(0xFFFFFFFF, p00, d);
                p01 += __shfl_xor_sync(0xFFFFFFFF, p01, d);
                p02 += __shfl_xor_sync(0xFFFFFFFF, p02, d);
                p10 += __shfl_xor_sync(0xFFFFFFFF, p10, d);
                p11 += __shfl_xor_sync(0xFFFFFFFF, p11, d);
                p12 += __shfl_xor_sync(0xFFFFFFFF, p12, d);
            }
            if (t == 0) {
                const int m0 = pt0 + wid * 16 + g;
                size_t o0 = ((size_t)b * NPTS + m0) * 3;
                size_t o1 = ((size_t)b * NPTS + m0 + 8) * 3;
                out[o0]     = p00 + SC[1152];
                out[o0 + 1] = p01 + SC[1153];
                out[o0 + 2] = p02 + SC[1154];
                out[o1]     = p10 + SC[1152];
                out[o1 + 1] = p11 + SC[1153];
                out[o1 + 2] = p12 + SC[1154];
            }
        }
    }
}

extern "C" void kernel_launch(void* const* d_in, const int* in_sizes, int n_in,
                              void* d_out, int out_size)
{
    const float* in0 = (const float*)d_in[0];
    const float* in1 = (const float*)d_in[1];
    float* out = (float*)d_out;   // [32, 32768, 3]

    wprep_kernel<<<BATCH * 3, 256>>>(in0, in1);

    dim3 grid(NPTS / PTS, BATCH);   // (512, 32)
    siren_mma_kernel<<<grid, THREADS>>>(in0, in1, out);
}